// round 4
// baseline (speedup 1.0000x reference)
#include <cuda_runtime.h>
#include <cuda_bf16.h>

// Shapes (fixed by problem)
#define B 4
#define QN 256
#define KN 1024
#define CIN 256     // Q_SIZE = K_SIZE = V_SIZE input feature dims
#define H 128

// Scratch for projected q/k (no cudaMalloc allowed)
__device__ float g_qp[B * QN * H];   // [row][h], row = b*QN+q
__device__ float g_kp[B * KN * H];   // [row][h], row = b*KN+k

__device__ __forceinline__ float tanh_approx(float x) {
    float y;
    asm("tanh.approx.f32 %0, %1;" : "=f"(y) : "f"(x));
    return y;
}

// ---------------------------------------------------------------------------
// Projection: out[row][h] = sum_c in[row][c] * W[h][c]
// block: 256 threads, 32 rows x 128 h. Each thread: 8 rows x 2 h.
// ---------------------------------------------------------------------------
__global__ void proj_kernel(const float* __restrict__ in,
                            const float* __restrict__ W,
                            int which /*0->g_qp, 1->g_kp*/) {
    __shared__ float Wt[32][130];   // [cc][h], padded (float2-aligned rows)
    __shared__ float ins[32][33];   // [r][cc]

    float* out = which ? g_kp : g_qp;
    const int tid = threadIdx.x;
    const int rowbase = blockIdx.x * 32;
    const int h0 = 2 * (tid & 63);   // this thread's h pair
    const int rg = tid >> 6;         // 0..3 -> rows rg*8 .. rg*8+7

    float acc[8][2];
#pragma unroll
    for (int i = 0; i < 8; i++) { acc[i][0] = 0.f; acc[i][1] = 0.f; }

    for (int cb = 0; cb < CIN; cb += 32) {
        __syncthreads();
        // W chunk transposed: 128 h x 32 c
#pragma unroll
        for (int i = 0; i < 16; i++) {
            int idx = i * 256 + tid;
            int h = idx >> 5, cc = idx & 31;
            Wt[cc][h] = W[h * CIN + cb + cc];
        }
        // input chunk: 32 rows x 32 c
#pragma unroll
        for (int i = 0; i < 4; i++) {
            int idx = i * 256 + tid;
            int r = idx >> 5, cc = idx & 31;
            ins[r][cc] = in[(rowbase + r) * CIN + cb + cc];
        }
        __syncthreads();
#pragma unroll
        for (int cc = 0; cc < 32; cc++) {
            float2 w = *(const float2*)&Wt[cc][h0];
#pragma unroll
            for (int i = 0; i < 8; i++) {
                float x = ins[rg * 8 + i][cc];
                acc[i][0] += x * w.x;
                acc[i][1] += x * w.y;
            }
        }
    }
#pragma unroll
    for (int i = 0; i < 8; i++) {
        int r = rowbase + rg * 8 + i;
        *(float2*)&out[r * H + h0] = make_float2(acc[i][0], acc[i][1]);
    }
}

// ---------------------------------------------------------------------------
// Fused scores + masked softmax + AV.
// Grid: B * (QN/4) blocks, 128 threads. Each block: 4 q rows.
//   Phase 1: scores[q][k] = sum_h w_v[h] * tanh(qp[q][h] + kp[k][h])
//            k-tiles of 128 staged in smem transposed [h][k]; thread = 2q x 2k.
//   Phase 2: masked softmax per row (1 warp / row).
//   Phase 3: out[q][v] = sum_{k<valid} p[q][k] * V[b][k][v]; thread owns v, v+128.
// ---------------------------------------------------------------------------
#define SM_KS   (128 * 130)          // k-proj tile, [h][k] pad 130
#define SM_SC   (4 * KN)             // scores [q][k]
#define SM_QS   (H * 4)              // q-proj tile transposed [h][q]
#define SM_WV   (H)
#define SMEM_FLOATS (SM_KS + SM_SC + SM_QS + SM_WV)

__global__ void attn_kernel(const float* __restrict__ values,
                            const int* __restrict__ valid_lens,
                            const float* __restrict__ w_v,
                            float* __restrict__ out) {
    extern __shared__ float sm[];
    float* ks  = sm;                       // [h][k] pad 130
    float* sc  = sm + SM_KS;               // [q][k]
    float* qs  = sc + SM_SC;               // [h][q] (4 q)
    float* wvs = qs + SM_QS;               // [h]

    const int tid = threadIdx.x;
    const int b = blockIdx.x >> 6;         // 64 q-tiles per batch
    const int qt = blockIdx.x & 63;
    const int rowq = b * QN + qt * 4;      // global q row of this tile
    const int valid = valid_lens[b];

    // Stage q tile (transposed) + w_v
    for (int i = tid; i < 4 * H; i += 128) {
        int q = i >> 7, h = i & 127;
        qs[h * 4 + q] = g_qp[(rowq + q) * H + h];
    }
    if (tid < H) wvs[tid] = w_v[tid];

    const int k0 = 2 * (tid & 63);         // k pair within tile
    const int q0 = 2 * (tid >> 6);         // q pair (0 or 2)

    for (int kb = 0; kb < valid; kb += 128) {
        __syncthreads();
        // Stage k-proj tile transposed: ks[h=tid][k=i]
        {
            const float* src = g_kp + (b * KN + kb) * H + tid;
            float* dst = ks + tid * 130;
#pragma unroll 8
            for (int i = 0; i < 128; i++) dst[i] = src[i * H];
        }
        __syncthreads();

        float a00 = 0.f, a01 = 0.f, a10 = 0.f, a11 = 0.f;
#pragma unroll 4
        for (int h = 0; h < H; h++) {
            float wv = wvs[h];
            float2 kk = *(const float2*)&ks[h * 130 + k0];
            float2 qq = *(const float2*)&qs[h * 4 + q0];
            a00 += wv * tanh_approx(qq.x + kk.x);
            a01 += wv * tanh_approx(qq.x + kk.y);
            a10 += wv * tanh_approx(qq.y + kk.x);
            a11 += wv * tanh_approx(qq.y + kk.y);
        }
        *(float2*)&sc[ q0      * KN + kb + k0] = make_float2(a00, a01);
        *(float2*)&sc[(q0 + 1) * KN + kb + k0] = make_float2(a10, a11);
    }
    __syncthreads();

    // Masked softmax: warp w handles row w (4 warps)
    {
        const int w = tid >> 5, lane = tid & 31;
        float* row = sc + w * KN;
        float m = -1e30f;
        for (int k = lane; k < valid; k += 32) m = fmaxf(m, row[k]);
#pragma unroll
        for (int off = 16; off; off >>= 1) m = fmaxf(m, __shfl_xor_sync(0xffffffffu, m, off));
        float s = 0.f;
        for (int k = lane; k < valid; k += 32) {
            float e = __expf(row[k] - m);
            row[k] = e;
            s += e;
        }
#pragma unroll
        for (int off = 16; off; off >>= 1) s += __shfl_xor_sync(0xffffffffu, s, off);
        float inv = 1.0f / s;
        for (int k = lane; k < valid; k += 32) row[k] *= inv;
    }
    __syncthreads();

    // AV: thread owns v = tid and v+128
    float o[4][2];
#pragma unroll
    for (int q = 0; q < 4; q++) { o[q][0] = 0.f; o[q][1] = 0.f; }
    const float* Vb = values + b * KN * 256;
    for (int k = 0; k < valid; k++) {
        float va = Vb[k * 256 + tid];
        float vb2 = Vb[k * 256 + tid + 128];
#pragma unroll
        for (int q = 0; q < 4; q++) {
            float p = sc[q * KN + k];
            o[q][0] += p * va;
            o[q][1] += p * vb2;
        }
    }
#pragma unroll
    for (int q = 0; q < 4; q++) {
        out[(rowq + q) * 256 + tid]       = o[q][0];
        out[(rowq + q) * 256 + tid + 128] = o[q][1];
    }
}

extern "C" void kernel_launch(void* const* d_in, const int* in_sizes, int n_in,
                              void* d_out, int out_size) {
    const float* queries    = (const float*)d_in[0];   // [B,QN,CIN]
    const float* keys       = (const float*)d_in[1];   // [B,KN,CIN]
    const float* values     = (const float*)d_in[2];   // [B,KN,256]
    const int*   valid_lens = (const int*)  d_in[3];   // [B]
    const float* W_q        = (const float*)d_in[4];   // [H,CIN]
    const float* W_k        = (const float*)d_in[5];   // [H,CIN]
    const float* w_v        = (const float*)d_in[6];   // [H]
    float* out = (float*)d_out;                        // [B,QN,256]

    (void)in_sizes; (void)n_in; (void)out_size;

    // Projections into device scratch
    proj_kernel<<<(B * QN) / 32, 256>>>(queries, W_q, 0);
    proj_kernel<<<(B * KN) / 32, 256>>>(keys,    W_k, 1);

    // Fused scores + softmax + AV
    const int smem_bytes = SMEM_FLOATS * (int)sizeof(float);
    cudaFuncSetAttribute(attn_kernel, cudaFuncAttributeMaxDynamicSharedMemorySize, smem_bytes);
    attn_kernel<<<B * (QN / 4), 128, smem_bytes>>>(values, valid_lens, w_v, out);
}

// round 6
// speedup vs baseline: 1.7880x; 1.7880x over previous
#include <cuda_runtime.h>
#include <cuda_bf16.h>

// Shapes (fixed by problem)
#define B   4
#define QN  256
#define KN  1024
#define CIN 256
#define H   128
#define VD  256
#define KTILE 128

// Scratch (no cudaMalloc allowed)
__device__ float g_qp[B * QN * H];     // [row][h]
__device__ float g_kpT[B * H * KN];    // [b][h][k]  (transposed!)

__device__ __forceinline__ float tanh_approx(float x) {
    float y;
    asm("tanh.approx.f32 %0, %1;" : "=f"(y) : "f"(x));
    return y;
}

// ---------------------------------------------------------------------------
// Merged projection. Blocks [0, 64): queries -> g_qp.  Blocks [64, 320): keys
// -> g_kpT (transposed [b][h][k]).  16 rows x 128 h per block, 256 threads,
// each thread 4 rows x 2 h.
// ---------------------------------------------------------------------------
#define QBLOCKS ((B * QN) / 16)   // 64
#define KBLOCKS ((B * KN) / 16)   // 256

__global__ __launch_bounds__(256) void proj_kernel(
        const float* __restrict__ queries, const float* __restrict__ keys,
        const float* __restrict__ W_q,     const float* __restrict__ W_k) {
    __shared__ float Wt[32][130];   // [cc][h]
    __shared__ float ins[16][33];   // [r][cc]

    const int tid = threadIdx.x;
    const bool is_q = (blockIdx.x < QBLOCKS);
    const float* in = is_q ? queries : keys;
    const float* W  = is_q ? W_q : W_k;
    const int rowbase = (is_q ? blockIdx.x : blockIdx.x - QBLOCKS) * 16;

    const int h0 = 2 * (tid & 63);   // h pair
    const int rg = tid >> 6;         // 0..3 -> rows rg*4 .. rg*4+3

    float acc[4][2];
#pragma unroll
    for (int i = 0; i < 4; i++) { acc[i][0] = 0.f; acc[i][1] = 0.f; }

    for (int cb = 0; cb < CIN; cb += 32) {
        __syncthreads();
#pragma unroll
        for (int i = 0; i < 16; i++) {          // W chunk: 128 h x 32 c
            int idx = i * 256 + tid;
            int h = idx >> 5, cc = idx & 31;
            Wt[cc][h] = W[h * CIN + cb + cc];
        }
        {                                        // input chunk: 16 rows x 32 c
            int idx = tid;
            int r = idx >> 5, cc = idx & 31;
            ins[r][cc] = in[(rowbase + r) * CIN + cb + cc];
            idx = 256 + tid;
            r = idx >> 5; cc = idx & 31;
            ins[r][cc] = in[(rowbase + r) * CIN + cb + cc];
        }
        __syncthreads();
#pragma unroll
        for (int cc = 0; cc < 32; cc++) {
            float2 w = *(const float2*)&Wt[cc][h0];
#pragma unroll
            for (int i = 0; i < 4; i++) {
                float x = ins[rg * 4 + i][cc];
                acc[i][0] += x * w.x;
                acc[i][1] += x * w.y;
            }
        }
    }

    if (is_q) {
#pragma unroll
        for (int i = 0; i < 4; i++) {
            int r = rowbase + rg * 4 + i;
            *(float2*)&g_qp[r * H + h0] = make_float2(acc[i][0], acc[i][1]);
        }
    } else {
#pragma unroll
        for (int i = 0; i < 4; i++) {
            int r = rowbase + rg * 4 + i;      // global key row
            int b = r >> 10;                   // r / KN
            int k = r & 1023;                  // r % KN
            g_kpT[(b * H + h0)     * KN + k] = acc[i][0];
            g_kpT[(b * H + h0 + 1) * KN + k] = acc[i][1];
        }
    }
}

// ---------------------------------------------------------------------------
// Fused scores + masked softmax + AV.
// Grid: B * (QN/4) = 256 blocks, 256 threads (8 warps). Block = 4 q rows.
//   Score: thread = 1q x 2k over 4q x 128k tile; k-proj tile copied from the
//          pre-transposed g_kpT (contiguous float4s, no transpose here).
//          q-proj + w_v hoisted to registers as float4 chunks of 8 h.
//   Scores stored [k][4q] so AV reads them with one broadcast LDS.128 per k.
//   Softmax: warp w (0..3) owns q row w.
//   AV: thread owns v = tid; unrolled x8 for MLP.
// ---------------------------------------------------------------------------
#define SM_KS (H * KTILE)      // 16384 floats
#define SM_SC (KN * 4)         // 4096 floats, layout [k][q]
#define SM_QS (4 * H)          // [q][h]
#define SM_WV (H)
#define SMEM_FLOATS (SM_KS + SM_SC + SM_QS + SM_WV)

__global__ __launch_bounds__(256) void attn_kernel(
        const float* __restrict__ values,
        const int*   __restrict__ valid_lens,
        const float* __restrict__ w_v,
        float*       __restrict__ out) {
    extern __shared__ float sm[];
    float* ks  = sm;             // [h][KTILE]
    float* sc  = sm + SM_KS;     // [k][4]
    float* qs  = sc + SM_SC;     // [q][h]
    float* wvs = qs + SM_QS;     // [h]

    const int tid = threadIdx.x;
    const int b  = blockIdx.x >> 6;
    const int qt = blockIdx.x & 63;
    const int rowq = b * QN + qt * 4;
    const int valid = valid_lens[b];

    // Stage q tile [q][h] + w_v
    for (int i = tid; i < 4 * H; i += 256) {
        int q = i >> 7, h = i & 127;
        qs[q * H + h] = g_qp[(rowq + q) * H + h];
    }
    if (tid < H) wvs[tid] = w_v[tid];

    const int q0  = tid >> 6;          // q row (0..3)
    const int kk0 = 2 * (tid & 63);    // k pair within tile
    const float* kbase = g_kpT + b * H * KN;

    for (int kb = 0; kb < valid; kb += KTILE) {
        __syncthreads();
        // Stage k-proj tile: ks[h][0..127] = g_kpT[b][h][kb..kb+127] (float4)
#pragma unroll
        for (int j = 0; j < 16; j++) {
            int i = j * 256 + tid;           // 0..4095 float4 index
            int h = i >> 5, kx = i & 31;
            ((float4*)ks)[h * 32 + kx] =
                *(const float4*)(kbase + h * KN + kb + kx * 4);
        }
        __syncthreads();

        float a0 = 0.f, a1 = 0.f;
#pragma unroll
        for (int hc = 0; hc < H; hc += 8) {
            float4 qA = *(const float4*)&qs[q0 * H + hc];
            float4 qB = *(const float4*)&qs[q0 * H + hc + 4];
            float4 wA = *(const float4*)&wvs[hc];
            float4 wB = *(const float4*)&wvs[hc + 4];
            const float* kr = ks + hc * KTILE + kk0;
            float2 kkv;
            kkv = *(const float2*)(kr + 0 * KTILE);
            a0 += wA.x * tanh_approx(qA.x + kkv.x);
            a1 += wA.x * tanh_approx(qA.x + kkv.y);
            kkv = *(const float2*)(kr + 1 * KTILE);
            a0 += wA.y * tanh_approx(qA.y + kkv.x);
            a1 += wA.y * tanh_approx(qA.y + kkv.y);
            kkv = *(const float2*)(kr + 2 * KTILE);
            a0 += wA.z * tanh_approx(qA.z + kkv.x);
            a1 += wA.z * tanh_approx(qA.z + kkv.y);
            kkv = *(const float2*)(kr + 3 * KTILE);
            a0 += wA.w * tanh_approx(qA.w + kkv.x);
            a1 += wA.w * tanh_approx(qA.w + kkv.y);
            kkv = *(const float2*)(kr + 4 * KTILE);
            a0 += wB.x * tanh_approx(qB.x + kkv.x);
            a1 += wB.x * tanh_approx(qB.x + kkv.y);
            kkv = *(const float2*)(kr + 5 * KTILE);
            a0 += wB.y * tanh_approx(qB.y + kkv.x);
            a1 += wB.y * tanh_approx(qB.y + kkv.y);
            kkv = *(const float2*)(kr + 6 * KTILE);
            a0 += wB.z * tanh_approx(qB.z + kkv.x);
            a1 += wB.z * tanh_approx(qB.z + kkv.y);
            kkv = *(const float2*)(kr + 7 * KTILE);
            a0 += wB.w * tanh_approx(qB.w + kkv.x);
            a1 += wB.w * tanh_approx(qB.w + kkv.y);
        }
        sc[(kb + kk0)     * 4 + q0] = a0;
        sc[(kb + kk0 + 1) * 4 + q0] = a1;
    }
    __syncthreads();

    // Masked softmax: warp w (0..3) owns q row w; scores at sc[k*4 + w]
    {
        const int w = tid >> 5, lane = tid & 31;
        if (w < 4) {
            float m = -1e30f;
            for (int k = lane; k < valid; k += 32) m = fmaxf(m, sc[k * 4 + w]);
#pragma unroll
            for (int off = 16; off; off >>= 1)
                m = fmaxf(m, __shfl_xor_sync(0xffffffffu, m, off));
            float s = 0.f;
            for (int k = lane; k < valid; k += 32) {
                float e = __expf(sc[k * 4 + w] - m);
                sc[k * 4 + w] = e;
                s += e;
            }
#pragma unroll
            for (int off = 16; off; off >>= 1)
                s += __shfl_xor_sync(0xffffffffu, s, off);
            float inv = 1.0f / s;
            for (int k = lane; k < valid; k += 32) sc[k * 4 + w] *= inv;
        }
    }
    __syncthreads();

    // AV: thread owns v = tid; 4 q accumulators; MLP-8 on V loads.
    float o0 = 0.f, o1 = 0.f, o2 = 0.f, o3 = 0.f;
    const float* Vb = values + b * KN * VD + tid;
    int k = 0;
    for (; k + 8 <= valid; k += 8) {
        float v[8];
#pragma unroll
        for (int kk = 0; kk < 8; kk++) v[kk] = Vb[(k + kk) * VD];
#pragma unroll
        for (int kk = 0; kk < 8; kk++) {
            float4 p = *(const float4*)&sc[(k + kk) * 4];
            o0 += p.x * v[kk];
            o1 += p.y * v[kk];
            o2 += p.z * v[kk];
            o3 += p.w * v[kk];
        }
    }
    for (; k < valid; k++) {
        float v = Vb[k * VD];
        float4 p = *(const float4*)&sc[k * 4];
        o0 += p.x * v; o1 += p.y * v; o2 += p.z * v; o3 += p.w * v;
    }
    out[(rowq + 0) * VD + tid] = o0;
    out[(rowq + 1) * VD + tid] = o1;
    out[(rowq + 2) * VD + tid] = o2;
    out[(rowq + 3) * VD + tid] = o3;
}

extern "C" void kernel_launch(void* const* d_in, const int* in_sizes, int n_in,
                              void* d_out, int out_size) {
    const float* queries    = (const float*)d_in[0];   // [B,QN,CIN]
    const float* keys       = (const float*)d_in[1];   // [B,KN,CIN]
    const float* values     = (const float*)d_in[2];   // [B,KN,VD]
    const int*   valid_lens = (const int*)  d_in[3];   // [B]
    const float* W_q        = (const float*)d_in[4];   // [H,CIN]
    const float* W_k        = (const float*)d_in[5];   // [H,CIN]
    const float* w_v        = (const float*)d_in[6];   // [H]
    float* out = (float*)d_out;                        // [B,QN,VD]

    (void)in_sizes; (void)n_in; (void)out_size;

    proj_kernel<<<QBLOCKS + KBLOCKS, 256>>>(queries, keys, W_q, W_k);

    const int smem_bytes = SMEM_FLOATS * (int)sizeof(float);
    cudaFuncSetAttribute(attn_kernel, cudaFuncAttributeMaxDynamicSharedMemorySize, smem_bytes);
    attn_kernel<<<B * (QN / 4), 256, smem_bytes>>>(values, valid_lens, w_v, out);
}